// round 7
// baseline (speedup 1.0000x reference)
#include <cuda_runtime.h>

#define NMIX 160
#define TPB  512
#define BM   64      // tokens per block
#define KC   64      // k chunk (phase 1)
#define BN2  64      // d tile (phase 2)

// smem layout (floats)
#define XK_PAD 68            // mod 32 = 4 (A-frag conflict-free)
#define W1_PAD 168           // mod 32 = 8 (B-frag conflict-free)
#define H_PAD  164           // mod 32 = 4
#define W2_PAD 72            // mod 32 = 8
#define XK_SZ  (BM * XK_PAD)          // 4352
#define OFF_W1 (2 * XK_SZ)            // 8704
#define W1_SZ  (KC * W1_PAD)          // 10752
#define HS_SZ  (BM * H_PAD)           // 10496 (aliases phase-1 buffers)
#define OFF_W2 HS_SZ
#define W2_SZ  (NMIX * W2_PAD)        // 11520
#define SMEM_FLOATS (OFF_W2 + 2 * W2_SZ)   // 33536 -> 134144 B

__device__ __forceinline__ float tf32r(float x) {
    unsigned u;
    asm("cvt.rna.tf32.f32 %0, %1;" : "=r"(u) : "f"(x));
    return __uint_as_float(u);
}

__device__ __forceinline__ void mma_tf32(float* c, const float4& a, const float2& b) {
    const unsigned* A = reinterpret_cast<const unsigned*>(&a);
    const unsigned* B = reinterpret_cast<const unsigned*>(&b);
    asm volatile(
        "mma.sync.aligned.m16n8k8.row.col.f32.tf32.tf32.f32 "
        "{%0,%1,%2,%3},{%4,%5,%6,%7},{%8,%9},{%0,%1,%2,%3};"
        : "+f"(c[0]), "+f"(c[1]), "+f"(c[2]), "+f"(c[3])
        : "r"(A[0]), "r"(A[1]), "r"(A[2]), "r"(A[3]), "r"(B[0]), "r"(B[1]));
}

// ---------------------------------------------------------------------------
// Fused kernel: state copy + (h = tanh(xk@W1)) + (out = x + sx*(maa + h@W2))
// grid = M/64 blocks, 512 threads = 16 warps (4m x 4n)
// ---------------------------------------------------------------------------
__global__ void __launch_bounds__(TPB) k_fused(
    const float* __restrict__ x, const float* __restrict__ state,
    const float* __restrict__ tmx, const float* __restrict__ W1,
    const float* __restrict__ W2,
    const float* __restrict__ mk, const float* __restrict__ mw,
    const float* __restrict__ mv, const float* __restrict__ mr,
    const float* __restrict__ mg,
    const int* __restrict__ i_ptr, float* __restrict__ out,
    float* __restrict__ out_state,
    int S, int D, int rows, int has_state, int total4, int nblocks)
{
    extern __shared__ float sm[];

    const int m0g  = blockIdx.x * BM;
    const int tid  = threadIdx.x;
    const int w    = tid >> 5;
    const int lane = tid & 31;
    const int wm   = w & 3;
    const int wn   = w >> 2;
    const int gq   = lane >> 2;
    const int tig  = lane & 3;
    const int i1   = rows * i_ptr[0] + 1;

    // ---- state copy (distributed) ----
    if (has_state) {
        for (int idx = blockIdx.x * TPB + tid; idx < total4; idx += nblocks * TPB) {
            int e  = idx * 4;
            int dd = e % D;
            int r  = (e / D) % rows;
            int b  = e / (D * rows);
            float4 v;
            if (r == i1)
                v = *(const float4*)&x[((size_t)b * S + (S - 1)) * D + dd];
            else
                v = *(const float4*)&state[e];
            *(float4*)&out_state[e] = v;
        }
    }

    // =================== PHASE 1: h = tanh(xk @ W1) =======================
    const int sa_m  = tid >> 4;          // 0..31 (+32 on 2nd iter)
    const int sa_kq = (tid & 15) * 4;

    float acc[5][4];
#pragma unroll
    for (int j = 0; j < 5; j++)
#pragma unroll
        for (int q = 0; q < 4; q++) acc[j][q] = 0.f;

    float4 xv[2], pv[2], tv[2];
    float4 wv[5];
    int    wk[5], wn4[5];

    const int nc = D / KC;

#define LDG1(KB)                                                              \
    {                                                                         \
        _Pragma("unroll")                                                     \
        for (int it = 0; it < 2; it++) {                                      \
            int m  = sa_m + it * 32;                                          \
            int mg = m0g + m;                                                 \
            int g  = (KB) + sa_kq;                                            \
            xv[it] = *(const float4*)&x[(size_t)mg * D + g];                  \
            if ((mg % S) == 0) {                                              \
                int b = mg / S;                                               \
                pv[it] = *(const float4*)&state[((size_t)b * rows + i1) * D + g]; \
            } else {                                                          \
                pv[it] = *(const float4*)&x[(size_t)(mg - 1) * D + g];        \
            }                                                                 \
            tv[it] = *(const float4*)&tmx[g];                                 \
        }                                                                     \
        _Pragma("unroll")                                                     \
        for (int it = 0; it < 5; it++) {                                      \
            int idx = tid + it * TPB;                                         \
            int k   = idx / 40;                                               \
            int n4  = (idx - k * 40) * 4;                                     \
            wk[it] = k; wn4[it] = n4;                                         \
            wv[it] = *(const float4*)&W1[(size_t)((KB) + k) * NMIX + n4];     \
        }                                                                     \
    }

#define STS1(BUF)                                                             \
    {                                                                         \
        float* xb = sm + (BUF) * XK_SZ;                                       \
        float* wb = sm + OFF_W1 + (BUF) * W1_SZ;                              \
        _Pragma("unroll")                                                     \
        for (int it = 0; it < 2; it++) {                                      \
            int m = sa_m + it * 32;                                           \
            float4 v;                                                         \
            v.x = tf32r(xv[it].x + (pv[it].x - xv[it].x) * tv[it].x);         \
            v.y = tf32r(xv[it].y + (pv[it].y - xv[it].y) * tv[it].y);         \
            v.z = tf32r(xv[it].z + (pv[it].z - xv[it].z) * tv[it].z);         \
            v.w = tf32r(xv[it].w + (pv[it].w - xv[it].w) * tv[it].w);         \
            *(float4*)&xb[m * XK_PAD + sa_kq] = v;                            \
        }                                                                     \
        _Pragma("unroll")                                                     \
        for (int it = 0; it < 5; it++) {                                      \
            float4 v;                                                         \
            v.x = tf32r(wv[it].x); v.y = tf32r(wv[it].y);                     \
            v.z = tf32r(wv[it].z); v.w = tf32r(wv[it].w);                     \
            *(float4*)&wb[wk[it] * W1_PAD + wn4[it]] = v;                     \
        }                                                                     \
    }

    LDG1(0);

    for (int c = 0; c < nc; c++) {
        STS1(c & 1);
        __syncthreads();
        if (c + 1 < nc) LDG1((c + 1) * KC);

        const float* xb = sm + (c & 1) * XK_SZ;
        const float* wb = sm + OFF_W1 + (c & 1) * W1_SZ;
        const int r0 = wm * 16 + gq;
#pragma unroll
        for (int ks = 0; ks < 8; ks++) {
            const int k0 = ks * 8;
            float4 af;
            af.x = xb[r0 * XK_PAD + k0 + tig];
            af.y = xb[(r0 + 8) * XK_PAD + k0 + tig];
            af.z = xb[r0 * XK_PAD + k0 + tig + 4];
            af.w = xb[(r0 + 8) * XK_PAD + k0 + tig + 4];
#pragma unroll
            for (int j = 0; j < 5; j++) {
                const int n = wn * 40 + j * 8 + gq;
                float2 b;
                b.x = wb[(k0 + tig) * W1_PAD + n];
                b.y = wb[(k0 + tig + 4) * W1_PAD + n];
                mma_tf32(acc[j], af, b);
            }
        }
        __syncthreads();   // reads of buf done before it is overwritten / h_s aliased
    }

    // h -> smem (aliases phase-1 buffers; all MMA reads complete)
    {
        float* hs = sm;    // [BM][H_PAD]
        const int r0 = wm * 16 + gq;
#pragma unroll
        for (int j = 0; j < 5; j++) {
            const int n = wn * 40 + j * 8 + tig * 2;
            hs[r0 * H_PAD + n]       = tf32r(tanhf(acc[j][0]));
            hs[r0 * H_PAD + n + 1]   = tf32r(tanhf(acc[j][1]));
            hs[(r0 + 8) * H_PAD + n]     = tf32r(tanhf(acc[j][2]));
            hs[(r0 + 8) * H_PAD + n + 1] = tf32r(tanhf(acc[j][3]));
        }
    }

    // =================== PHASE 2: out = x + sx*(maa + h@W2) ================
    const float* maa[5] = { mk, mw, mv, mr, mg };
    const int ntiles = D / BN2;
    float4 w2v[5];

#define LDG2(T)                                                               \
    {                                                                         \
        _Pragma("unroll")                                                     \
        for (int it = 0; it < 5; it++) {                                      \
            int idx = tid + it * TPB;                                         \
            int k   = idx >> 4;                                               \
            int n4  = (idx & 15) * 4;                                         \
            w2v[it] = *(const float4*)&W2[(size_t)k * D + (T) * BN2 + n4];    \
        }                                                                     \
    }

#define STS2(BUF)                                                             \
    {                                                                         \
        float* wb2 = sm + OFF_W2 + (BUF) * W2_SZ;                             \
        _Pragma("unroll")                                                     \
        for (int it = 0; it < 5; it++) {                                      \
            int idx = tid + it * TPB;                                         \
            int k   = idx >> 4;                                               \
            int n4  = (idx & 15) * 4;                                         \
            float4 v;                                                         \
            v.x = tf32r(w2v[it].x); v.y = tf32r(w2v[it].y);                   \
            v.z = tf32r(w2v[it].z); v.w = tf32r(w2v[it].w);                   \
            *(float4*)&wb2[k * W2_PAD + n4] = v;                              \
        }                                                                     \
    }

    LDG2(0);

    for (int t = 0; t < ntiles; t++) {
        STS2(t & 1);
        __syncthreads();            // also makes h_s visible on first iteration
        if (t + 1 < ntiles) LDG2(t + 1);

        const float* hs  = sm;
        const float* wb2 = sm + OFF_W2 + (t & 1) * W2_SZ;
        const int d0 = t * BN2;
        const int r0 = wm * 16 + gq;

        float a2[5][2][4];
#pragma unroll
        for (int f = 0; f < 5; f++)
#pragma unroll
            for (int j = 0; j < 2; j++)
#pragma unroll
                for (int q = 0; q < 4; q++) a2[f][j][q] = 0.f;

#pragma unroll
        for (int f = 0; f < 5; f++) {
#pragma unroll
            for (int ks = 0; ks < 4; ks++) {
                const int kc = f * 32 + ks * 8;
                float4 af;
                af.x = hs[r0 * H_PAD + kc + tig];
                af.y = hs[(r0 + 8) * H_PAD + kc + tig];
                af.z = hs[r0 * H_PAD + kc + tig + 4];
                af.w = hs[(r0 + 8) * H_PAD + kc + tig + 4];
#pragma unroll
                for (int j = 0; j < 2; j++) {
                    const int n = wn * 16 + j * 8 + gq;
                    float2 b;
                    b.x = wb2[(kc + tig) * W2_PAD + n];
                    b.y = wb2[(kc + tig + 4) * W2_PAD + n];
                    mma_tf32(a2[f][j], af, b);
                }
            }
        }

        // epilogue: f innermost; x/prev loaded once per (j,half)
#pragma unroll
        for (int j = 0; j < 2; j++) {
            const int d = d0 + wn * 16 + j * 8 + tig * 2;
            float2 m2[5];
#pragma unroll
            for (int f = 0; f < 5; f++) m2[f] = *(const float2*)&maa[f][d];
#pragma unroll
            for (int half = 0; half < 2; half++) {
                const int mr_ = m0g + wm * 16 + gq + half * 8;
                const float2 xvv = *(const float2*)&x[(size_t)mr_ * D + d];
                float2 pvv;
                if ((mr_ % S) == 0) {
                    int b = mr_ / S;
                    pvv = *(const float2*)&state[((size_t)b * rows + i1) * D + d];
                } else {
                    pvv = *(const float2*)&x[(size_t)(mr_ - 1) * D + d];
                }
                const float sx0 = pvv.x - xvv.x;
                const float sx1 = pvv.y - xvv.y;
#pragma unroll
                for (int f = 0; f < 5; f++) {
                    float2 o;
                    o.x = xvv.x + sx0 * (m2[f].x + a2[f][j][half * 2]);
                    o.y = xvv.y + sx1 * (m2[f].y + a2[f][j][half * 2 + 1]);
                    *(float2*)&out[((size_t)mr_ * 5 + f) * D + d] = o;
                }
            }
        }
        __syncthreads();   // all reads of wb2 buf done before next overwrite
    }
#undef LDG1
#undef STS1
#undef LDG2
#undef STS2
}

// ---------------------------------------------------------------------------
extern "C" void kernel_launch(void* const* d_in, const int* in_sizes, int n_in,
                              void* d_out, int out_size)
{
    const float* x     = (const float*)d_in[0];
    const float* state = (const float*)d_in[1];
    const float* tmx   = (const float*)d_in[2];
    const float* W1    = (const float*)d_in[3];
    const float* W2    = (const float*)d_in[4];
    const float* mk    = (const float*)d_in[5];
    const float* mw    = (const float*)d_in[6];
    const float* mv    = (const float*)d_in[7];
    const float* mr    = (const float*)d_in[8];
    const float* mg    = (const float*)d_in[9];
    const int*   ip    = (const int*)d_in[10];

    const int D    = in_sizes[2];          // 2048
    const int M    = in_sizes[0] / D;      // 8192
    const int rows = 2 + D / 32;           // 66
    const int B    = in_sizes[1] / (rows * D);
    const int S    = M / B;

    float* out_x = (float*)d_out;
    const long long xsz = (long long)M * 5 * D;
    const int has_state = ((long long)out_size > xsz) ? 1 : 0;
    float* out_state = out_x + xsz;
    const int total4 = (B * rows * D) / 4;
    const int nblocks = M / BM;

    const int smem = SMEM_FLOATS * 4;      // 134144 B
    static int inited = 0;
    if (!inited) {
        cudaFuncSetAttribute(k_fused, cudaFuncAttributeMaxDynamicSharedMemorySize, smem);
        inited = 1;
    }

    k_fused<<<nblocks, TPB, smem>>>(x, state, tmx, W1, W2,
                                    mk, mw, mv, mr, mg, ip,
                                    out_x, out_state,
                                    S, D, rows, has_state, total4, nblocks);
}

// round 8
// speedup vs baseline: 1.0760x; 1.0760x over previous
#include <cuda_runtime.h>

#define NMIX 160
// gemm1: 64m x 160n, KC=64, 512 threads = 4m x 4n warps, j=5
#define T1    512
#define BM1   64
#define KC1   64
#define A1PAD 68     // mod 32 = 4  (A-frag conflict-free)
#define B1PAD 168    // mod 32 = 8  (B-frag conflict-free)
#define XK_SZ (BM1 * A1PAD)
#define W1_SZ (KC1 * B1PAD)
#define SM1_FLOATS (2 * XK_SZ + 2 * W1_SZ)       // 30208 -> 120832 B
// gemm2: W2-resident d-stripe blocks; 32-token m-tiles
#define T2    256
#define BMI   32
#define BN2   64
#define NG    8
#define HPAD  164    // mod 32 = 4
#define WPAD  72     // mod 32 = 8
#define HB_SZ (BMI * HPAD)                        // 5248
#define W2_SZ (NMIX * WPAD)                       // 11520
#define SM2_FLOATS (W2_SZ + 2 * HB_SZ)            // 22016 -> 88064 B

// h = tanh(xk @ W1): [M][NMIX], M = 8192
__device__ float g_h[8192 * NMIX];

__device__ __forceinline__ void mma_tf32(float* c, const float4& a, const float2& b) {
    const unsigned* A = reinterpret_cast<const unsigned*>(&a);
    const unsigned* B = reinterpret_cast<const unsigned*>(&b);
    asm volatile(
        "mma.sync.aligned.m16n8k8.row.col.f32.tf32.tf32.f32 "
        "{%0,%1,%2,%3},{%4,%5,%6,%7},{%8,%9},{%0,%1,%2,%3};"
        : "+f"(c[0]), "+f"(c[1]), "+f"(c[2]), "+f"(c[3])
        : "r"(A[0]), "r"(A[1]), "r"(A[2]), "r"(A[3]), "r"(B[0]), "r"(B[1]));
}

// ---------------------------------------------------------------------------
// GEMM1: g_h[m,n] = tanh( sum_k xk[m,k] * W1[k,n] )
// single barrier per chunk; raw f32 operands (HW tf32 truncation)
// ---------------------------------------------------------------------------
__global__ void __launch_bounds__(T1, 1) k_gemm1(
    const float* __restrict__ x, const float* __restrict__ state,
    const float* __restrict__ tmx, const float* __restrict__ W1,
    const int* __restrict__ i_ptr, int S, int D, int rows)
{
    extern __shared__ float sm[];

    const int m0g  = blockIdx.x * BM1;
    const int tid  = threadIdx.x;
    const int w    = tid >> 5;
    const int lane = tid & 31;
    const int wm   = w & 3;
    const int wn   = w >> 2;
    const int gq   = lane >> 2;
    const int tig  = lane & 3;
    const int i1   = rows * i_ptr[0] + 1;

    const int sa_m  = tid >> 4;          // 0..31 (+32 on 2nd iter)
    const int sa_kq = (tid & 15) * 4;

    float acc[5][4];
#pragma unroll
    for (int j = 0; j < 5; j++)
#pragma unroll
        for (int q = 0; q < 4; q++) acc[j][q] = 0.f;

    float4 xv[2], pv[2], tv[2];
    float4 wv[5];
    int    wk[5], wn4[5];

    const int nc = D / KC1;

#define LDG1(KB)                                                              \
    {                                                                         \
        _Pragma("unroll")                                                     \
        for (int it = 0; it < 2; it++) {                                      \
            int m  = sa_m + it * 32;                                          \
            int mg = m0g + m;                                                 \
            int g  = (KB) + sa_kq;                                            \
            xv[it] = *(const float4*)&x[(size_t)mg * D + g];                  \
            if ((mg % S) == 0) {                                              \
                int b = mg / S;                                               \
                pv[it] = *(const float4*)&state[((size_t)b * rows + i1) * D + g]; \
            } else {                                                          \
                pv[it] = *(const float4*)&x[(size_t)(mg - 1) * D + g];        \
            }                                                                 \
            tv[it] = *(const float4*)&tmx[g];                                 \
        }                                                                     \
        _Pragma("unroll")                                                     \
        for (int it = 0; it < 5; it++) {                                      \
            int idx = tid + it * T1;                                          \
            int k   = idx / 40;                                               \
            int n4  = (idx - k * 40) * 4;                                     \
            wk[it] = k; wn4[it] = n4;                                         \
            wv[it] = *(const float4*)&W1[(size_t)((KB) + k) * NMIX + n4];     \
        }                                                                     \
    }

#define STS1(BUF)                                                             \
    {                                                                         \
        float* xb = sm + (BUF) * XK_SZ;                                       \
        float* wb = sm + 2 * XK_SZ + (BUF) * W1_SZ;                           \
        _Pragma("unroll")                                                     \
        for (int it = 0; it < 2; it++) {                                      \
            int m = sa_m + it * 32;                                           \
            float4 v;                                                         \
            v.x = xv[it].x + (pv[it].x - xv[it].x) * tv[it].x;                \
            v.y = xv[it].y + (pv[it].y - xv[it].y) * tv[it].y;                \
            v.z = xv[it].z + (pv[it].z - xv[it].z) * tv[it].z;                \
            v.w = xv[it].w + (pv[it].w - xv[it].w) * tv[it].w;                \
            *(float4*)&xb[m * A1PAD + sa_kq] = v;                             \
        }                                                                     \
        _Pragma("unroll")                                                     \
        for (int it = 0; it < 5; it++)                                        \
            *(float4*)&wb[wk[it] * B1PAD + wn4[it]] = wv[it];                 \
    }

    LDG1(0);

    for (int c = 0; c < nc; c++) {
        STS1(c & 1);
        __syncthreads();
        if (c + 1 < nc) LDG1((c + 1) * KC1);

        const float* xb = sm + (c & 1) * XK_SZ;
        const float* wb = sm + 2 * XK_SZ + (c & 1) * W1_SZ;
        const int r0 = wm * 16 + gq;
#pragma unroll
        for (int ks = 0; ks < 8; ks++) {
            const int k0 = ks * 8;
            float4 af;
            af.x = xb[r0 * A1PAD + k0 + tig];
            af.y = xb[(r0 + 8) * A1PAD + k0 + tig];
            af.z = xb[r0 * A1PAD + k0 + tig + 4];
            af.w = xb[(r0 + 8) * A1PAD + k0 + tig + 4];
#pragma unroll
            for (int j = 0; j < 5; j++) {
                const int n = wn * 40 + j * 8 + gq;
                float2 b;
                b.x = wb[(k0 + tig) * B1PAD + n];
                b.y = wb[(k0 + tig + 4) * B1PAD + n];
                mma_tf32(acc[j], af, b);
            }
        }
    }

    const int r0g = m0g + wm * 16 + gq;
#pragma unroll
    for (int j = 0; j < 5; j++) {
        const int n = wn * 40 + j * 8 + tig * 2;
        *(float2*)&g_h[(size_t)r0g * NMIX + n] =
            make_float2(tanhf(acc[j][0]), tanhf(acc[j][1]));
        *(float2*)&g_h[(size_t)(r0g + 8) * NMIX + n] =
            make_float2(tanhf(acc[j][2]), tanhf(acc[j][3]));
    }
#undef LDG1
#undef STS1
}

// ---------------------------------------------------------------------------
// GEMM2 fused: out[m,f,d] = x + sx*(maa_f + h_f @ W2_f)
// grid (NG m-groups, D/64 d-tiles); W2 tile resident in smem; 32-token
// m-tiles streamed with double-buffered h; state copy folded in.
// ---------------------------------------------------------------------------
__global__ void __launch_bounds__(T2, 2) k_gemm2(
    const float* __restrict__ x, const float* __restrict__ state,
    const float* __restrict__ W2,
    const float* __restrict__ mk, const float* __restrict__ mw,
    const float* __restrict__ mv, const float* __restrict__ mr,
    const float* __restrict__ mg,
    const int* __restrict__ i_ptr, float* __restrict__ out,
    float* __restrict__ out_state,
    int S, int D, int rows, int has_state, int total4, int niter)
{
    extern __shared__ float sm[];
    float* w2s = sm;                 // [160][WPAD]
    float* hb0 = sm + W2_SZ;         // [2][BMI][HPAD]

    const int d0   = blockIdx.y * BN2;
    const int tid  = threadIdx.x;
    const int w    = tid >> 5;
    const int lane = tid & 31;
    const int wm   = w & 1;          // 2 m-groups of 16
    const int wn   = w >> 1;         // 4 n-groups of 16
    const int gq   = lane >> 2;
    const int tig  = lane & 3;
    const int i1   = rows * i_ptr[0] + 1;

    // ---- state copy (distributed over all blocks) ----
    if (has_state) {
        const int nb = NG * (D / BN2);
        for (int idx = (blockIdx.y * NG + blockIdx.x) * T2 + tid; idx < total4;
             idx += nb * T2) {
            int e  = idx * 4;
            int dd = e % D;
            int r  = (e / D) % rows;
            int b  = e / (D * rows);
            float4 v;
            if (r == i1)
                v = *(const float4*)&x[((size_t)b * S + (S - 1)) * D + dd];
            else
                v = *(const float4*)&state[e];
            *(float4*)&out_state[e] = v;
        }
    }

    // ---- stage W2 tile once: 160 x 64 ----
#pragma unroll
    for (int it = 0; it < 10; it++) {
        int idx = tid + it * T2;
        int k   = idx >> 4;
        int n4  = (idx & 15) * 4;
        *(float4*)&w2s[k * WPAD + n4] = *(const float4*)&W2[(size_t)k * D + d0 + n4];
    }

    const float* maa[5] = { mk, mw, mv, mr, mg };
    const int tbase = blockIdx.x * niter;

    // h staging regs: 5 float4 per thread
    float4 hv[5];
    const int sh_r  = tid / 40;                    // may be 6 rows per pass? use idx form
    (void)sh_r;

#define LDGH(T)                                                               \
    {                                                                         \
        const int m0_ = (tbase + (T)) * BMI;                                  \
        _Pragma("unroll")                                                     \
        for (int it = 0; it < 5; it++) {                                      \
            int idx = tid + it * T2;                                          \
            int r   = idx / 40;                                               \
            int c4  = (idx - r * 40) * 4;                                     \
            hv[it] = *(const float4*)&g_h[(size_t)(m0_ + r) * NMIX + c4];     \
        }                                                                     \
    }

#define STSH(BUF)                                                             \
    {                                                                         \
        float* hb = hb0 + (BUF) * HB_SZ;                                      \
        _Pragma("unroll")                                                     \
        for (int it = 0; it < 5; it++) {                                      \
            int idx = tid + it * T2;                                          \
            int r   = idx / 40;                                               \
            int c4  = (idx - r * 40) * 4;                                     \
            *(float4*)&hb[r * HPAD + c4] = hv[it];                            \
        }                                                                     \
    }

    LDGH(0);

    for (int t = 0; t < niter; t++) {
        STSH(t & 1);
        __syncthreads();
        if (t + 1 < niter) LDGH(t + 1);

        const float* hb = hb0 + (t & 1) * HB_SZ;
        const int m0 = (tbase + t) * BMI;
        const int r0 = wm * 16 + gq;

        float acc[5][2][4];
#pragma unroll
        for (int f = 0; f < 5; f++)
#pragma unroll
            for (int j = 0; j < 2; j++)
#pragma unroll
                for (int q = 0; q < 4; q++) acc[f][j][q] = 0.f;

#pragma unroll
        for (int f = 0; f < 5; f++) {
#pragma unroll
            for (int ks = 0; ks < 4; ks++) {
                const int kc = f * 32 + ks * 8;
                float4 af;
                af.x = hb[r0 * HPAD + kc + tig];
                af.y = hb[(r0 + 8) * HPAD + kc + tig];
                af.z = hb[r0 * HPAD + kc + tig + 4];
                af.w = hb[(r0 + 8) * HPAD + kc + tig + 4];
#pragma unroll
                for (int j = 0; j < 2; j++) {
                    const int n = wn * 16 + j * 8 + gq;
                    float2 b;
                    b.x = w2s[(kc + tig) * WPAD + n];
                    b.y = w2s[(kc + tig + 4) * WPAD + n];
                    mma_tf32(acc[f][j], af, b);
                }
            }
        }

        // epilogue: f innermost; x/prev loaded once per (j,half)
#pragma unroll
        for (int j = 0; j < 2; j++) {
            const int d = d0 + wn * 16 + j * 8 + tig * 2;
            float2 m2[5];
#pragma unroll
            for (int f = 0; f < 5; f++) m2[f] = *(const float2*)&maa[f][d];
#pragma unroll
            for (int half = 0; half < 2; half++) {
                const int mr_ = m0 + wm * 16 + gq + half * 8;
                const float2 xvv = *(const float2*)&x[(size_t)mr_ * D + d];
                float2 pvv;
                if ((mr_ % S) == 0) {
                    int b = mr_ / S;
                    pvv = *(const float2*)&state[((size_t)b * rows + i1) * D + d];
                } else {
                    pvv = *(const float2*)&x[(size_t)(mr_ - 1) * D + d];
                }
                const float sx0 = pvv.x - xvv.x;
                const float sx1 = pvv.y - xvv.y;
#pragma unroll
                for (int f = 0; f < 5; f++) {
                    float2 o;
                    o.x = xvv.x + sx0 * (m2[f].x + acc[f][j][half * 2]);
                    o.y = xvv.y + sx1 * (m2[f].y + acc[f][j][half * 2 + 1]);
                    *(float2*)&out[((size_t)mr_ * 5 + f) * D + d] = o;
                }
            }
        }
    }
#undef LDGH
#undef STSH
}

// ---------------------------------------------------------------------------
extern "C" void kernel_launch(void* const* d_in, const int* in_sizes, int n_in,
                              void* d_out, int out_size)
{
    const float* x     = (const float*)d_in[0];
    const float* state = (const float*)d_in[1];
    const float* tmx   = (const float*)d_in[2];
    const float* W1    = (const float*)d_in[3];
    const float* W2    = (const float*)d_in[4];
    const float* mk    = (const float*)d_in[5];
    const float* mw    = (const float*)d_in[6];
    const float* mv    = (const float*)d_in[7];
    const float* mr    = (const float*)d_in[8];
    const float* mg    = (const float*)d_in[9];
    const int*   ip    = (const int*)d_in[10];

    const int D    = in_sizes[2];          // 2048
    const int M    = in_sizes[0] / D;      // 8192
    const int rows = 2 + D / 32;           // 66
    const int B    = in_sizes[1] / (rows * D);
    const int S    = M / B;

    float* out_x = (float*)d_out;
    const long long xsz = (long long)M * 5 * D;
    const int has_state = ((long long)out_size > xsz) ? 1 : 0;
    float* out_state = out_x + xsz;
    const int total4 = (B * rows * D) / 4;
    const int niter = M / BMI / NG;        // 32

    const int smem1 = SM1_FLOATS * 4;      // 120832 B
    const int smem2 = SM2_FLOATS * 4;      // 88064 B
    static int inited = 0;
    if (!inited) {
        cudaFuncSetAttribute(k_gemm1, cudaFuncAttributeMaxDynamicSharedMemorySize, smem1);
        cudaFuncSetAttribute(k_gemm2, cudaFuncAttributeMaxDynamicSharedMemorySize, smem2);
        inited = 1;
    }

    k_gemm1<<<M / BM1, T1, smem1>>>(x, state, tmx, W1, ip, S, D, rows);

    dim3 g2(NG, D / BN2);
    k_gemm2<<<g2, T2, smem2>>>(x, state, W2, mk, mw, mv, mr, mg, ip,
                               out_x, out_state, S, D, rows,
                               has_state, total4, niter);
}